// round 1
// baseline (speedup 1.0000x reference)
#include <cuda_runtime.h>
#include <math.h>

#define DINLINE __device__ __forceinline__

constexpr int NN = 100000;   // nodes
constexpr int TT = 24;       // time steps
constexpr int EE = 3200000;  // edges

// ----------------------------------------------------------------------------
// Scratch (static device globals; no allocations allowed)
// ----------------------------------------------------------------------------
__device__ __align__(16) float g_xw[NN * 32];      // linear output / spmm input
__device__ __align__(16) float g_acc[NN * 32];     // spmm accumulator
__device__ __align__(16) float g_gi[NN * 192];     // time-invariant input-gate projections (+bias)
__device__ __align__(16) float g_h[2][NN * 64];    // double-buffered GRU state
__device__ __align__(16) float g_WhhT[64 * 192];   // W_hh transposed: [k][j]  (j order: r|z|n)
__device__ __align__(16) float g_Wih8T[8 * 192];   // W_ih[:,32:40] transposed: [k8][j]
__device__ __align__(16) float g_h1wT[64 * 64];    // h1_W transposed: [k][j]
__device__ __align__(16) float g_bhn[64];          // b_hh[128:192]

DINLINE float sigf(float x)  { return __fdividef(1.0f, 1.0f + __expf(-x)); }
DINLINE float tanhx(float x) { return __fdividef(2.0f, 1.0f + __expf(-2.0f * x)) - 1.0f; }

// ----------------------------------------------------------------------------
// Zeroing kernels (grid sizes are exact multiples; no bounds checks needed)
// ----------------------------------------------------------------------------
__global__ void zero_acc_kernel() {
    int i = blockIdx.x * 256 + threadIdx.x;   // grid = 12500*256 = N*32 exactly
    g_acc[i] = 0.0f;
}
__global__ void zero_h0_kernel() {
    int i = blockIdx.x * 256 + threadIdx.x;   // grid = 25000*256 = N*64 exactly
    g_h[0][i] = 0.0f;
}

// ----------------------------------------------------------------------------
// Dense 32->32 linear: g_xw[n][j] = src[n][:] @ W[j][:]^T + b[j]
// src = Xext (layer 1) or relu(g_acc) (layer 2). 8 nodes / 256-thread block.
// ----------------------------------------------------------------------------
__global__ void lin32_kernel(const float* __restrict__ Xext,
                             const float* __restrict__ W,
                             const float* __restrict__ bias,
                             int relu_acc_src) {
    __shared__ float Wt[1024];   // Wt[k*32+j] = W[j][k]
    __shared__ float Xs[256];    // 8 nodes x 32 feats
    int tid = threadIdx.x;
    int n0  = blockIdx.x * 8;

    for (int e = tid; e < 1024; e += 256) {
        int j = e >> 5, k = e & 31;
        Wt[k * 32 + j] = W[j * 32 + k];
    }
    {
        float v;
        if (relu_acc_src) v = fmaxf(g_acc[n0 * 32 + tid], 0.0f);
        else              v = Xext[n0 * 32 + tid];
        Xs[tid] = v;
    }
    __syncthreads();

    int n = tid >> 5, j = tid & 31;
    float acc = bias[j];
#pragma unroll
    for (int k = 0; k < 32; ++k)
        acc = fmaf(Xs[n * 32 + k], Wt[k * 32 + j], acc);
    g_xw[(n0 + n) * 32 + j] = acc;
}

// ----------------------------------------------------------------------------
// SpMM scatter: g_acc[row] += val * g_xw[col], one warp per edge (lane = feature).
// grid = E*32/256 = 400000 blocks exactly.
// ----------------------------------------------------------------------------
__global__ void spmm_kernel(const int*  __restrict__ er,
                            const int*  __restrict__ ec,
                            const float* __restrict__ ev) {
    int idx = blockIdx.x * 256 + threadIdx.x;
    int e = idx >> 5, f = idx & 31;
    int r = er[e];
    int c = ec[e];
    float v = ev[e];
    atomicAdd(&g_acc[r * 32 + f], v * g_xw[c * 32 + f]);
}

// ----------------------------------------------------------------------------
// gi_static[n][j] = relu(g_acc[n]) @ W_ih[j,0:32]^T + b_ih[j] + (j<128 ? b_hh[j] : 0)
// 32 nodes / 256-thread block; grid = 3125 exactly.
// ----------------------------------------------------------------------------
__global__ void gi_static_kernel(const float* __restrict__ Wih,
                                 const float* __restrict__ bih,
                                 const float* __restrict__ bhh) {
    __shared__ float Ws[32 * 192];   // Ws[k*192+j] = W_ih[j][k]
    __shared__ float Hs[32 * 33];    // relu'd h tile, padded rows
    int tid = threadIdx.x;
    int n0  = blockIdx.x * 32;

    for (int e = tid; e < 6144; e += 256) {
        int k = e / 192, j = e - k * 192;
        Ws[e] = Wih[j * 40 + k];
    }
    for (int e = tid; e < 1024; e += 256) {
        int n = e >> 5, k = e & 31;
        Hs[n * 33 + k] = fmaxf(g_acc[(n0 + n) * 32 + k], 0.0f);
    }
    __syncthreads();

#pragma unroll 1
    for (int it = 0; it < 24; ++it) {
        int p = it * 256 + tid;        // 32*192 = 6144 = 24*256
        int n = p / 192, j = p - n * 192;
        float acc = bih[j] + (j < 128 ? bhh[j] : 0.0f);
#pragma unroll
        for (int k = 0; k < 32; ++k)
            acc = fmaf(Hs[n * 33 + k], Ws[k * 192 + j], acc);
        g_gi[(n0 + n) * 192 + j] = acc;
    }
}

// ----------------------------------------------------------------------------
// Transpose weights once per launch into fast-load layouts.
// ----------------------------------------------------------------------------
__global__ void prep_weights_kernel(const float* __restrict__ Whh,
                                    const float* __restrict__ Wih,
                                    const float* __restrict__ h1W,
                                    const float* __restrict__ bhh) {
    int id = blockIdx.x * 512 + threadIdx.x;
    if (id < 12288) {                       // W_hh: [192][64] -> [64][192]
        int k = id / 192, j = id - k * 192;
        g_WhhT[id] = Whh[j * 64 + k];
    } else if (id < 13824) {                // W_ih cols 32..39: [192][8] -> [8][192]
        int q = id - 12288;
        int k = q / 192, j = q - k * 192;
        g_Wih8T[q] = Wih[j * 40 + 32 + k];
    } else if (id < 17920) {                // h1_W: [64][64] -> [64][64] transposed
        int q = id - 13824;
        int k = q >> 6, j = q & 63;
        g_h1wT[q] = h1W[j * 64 + k];
    } else if (id < 17984) {
        g_bhn[id - 17920] = bhh[128 + id - 17920];
    }
}

// ----------------------------------------------------------------------------
// Fused GRU step + MLP head. 128 nodes / 512-thread block.
// Thread (ng = tid&31, hg = tid>>5) owns 4 nodes x 4 hidden units x {r,z,in,hn}.
// ----------------------------------------------------------------------------
constexpr int SMEM_FLOATS = 9216 + 12288 + 1536 + 4096 + 64 + 64 + 64 + 4;
constexpr int SMEM_BYTES  = SMEM_FLOATS * 4;   // 109,332 B

__global__ void __launch_bounds__(512, 1)
gru_step_kernel(const float* __restrict__ xdyn_t,   // X_dyn_mean + t*N*8
                const float* __restrict__ h1b,
                const float* __restrict__ h2w,
                const float* __restrict__ h2b,
                float* __restrict__ yout,           // d_out + t*N
                int parity) {
    extern __shared__ float sm[];
    float* s_zt   = sm;                 // [72][128]  (reused as hnew [64][128] later)
    float* s_whh  = sm + 9216;          // [64][192]
    float* s_wih8 = s_whh + 12288;      // [8][192]
    float* s_h1w  = s_wih8 + 1536;      // [64][64]
    float* s_bhn  = s_h1w + 4096;       // 64
    float* s_h1b  = s_bhn + 64;         // 64
    float* s_h2w  = s_h1b + 64;         // 64
    float* s_h2b  = s_h2w + 64;         // 1

    const float* hprev = g_h[parity];
    float*       hnext = g_h[parity ^ 1];
    int tid = threadIdx.x;
    int n0  = blockIdx.x * 128;

    // ---- prologue: weights ----
    {
        float4* d4; const float4* s4;
        d4 = (float4*)s_whh;  s4 = (const float4*)g_WhhT;
        for (int i = tid; i < 3072; i += 512) d4[i] = s4[i];
        d4 = (float4*)s_wih8; s4 = (const float4*)g_Wih8T;
        if (tid < 384) d4[tid] = s4[tid];
        d4 = (float4*)s_h1w;  s4 = (const float4*)g_h1wT;
        for (int i = tid; i < 1024; i += 512) d4[i] = s4[i];
        if (tid < 64) { s_bhn[tid] = g_bhn[tid]; s_h1b[tid] = h1b[tid]; s_h2w[tid] = h2w[tid]; }
        if (tid == 0) s_h2b[0] = h2b[0];
    }
    // ---- prologue: input tile, transposed [k][node] ----
    {
        int nl = tid >> 2, qp = tid & 3;
        int gn = min(n0 + nl, NN - 1);
        const float4* hp4 = (const float4*)hprev;
#pragma unroll
        for (int q = 0; q < 4; ++q) {
            int k0 = qp * 16 + q * 4;
            float4 v = hp4[gn * 16 + (k0 >> 2)];
            s_zt[(k0 + 0) * 128 + nl] = v.x;
            s_zt[(k0 + 1) * 128 + nl] = v.y;
            s_zt[(k0 + 2) * 128 + nl] = v.z;
            s_zt[(k0 + 3) * 128 + nl] = v.w;
        }
        if (tid < 128) {
            int gn2 = min(n0 + tid, NN - 1);
            const float4* x4 = (const float4*)(xdyn_t + gn2 * 8);
            float4 a = x4[0], b = x4[1];
            float* dst = s_zt + 64 * 128 + tid;
            dst[0] = a.x; dst[128] = a.y; dst[256] = a.z; dst[384] = a.w;
            dst[512] = b.x; dst[640] = b.y; dst[768] = b.z; dst[896] = b.w;
        }
    }
    __syncthreads();

    int ng = tid & 31, hg = tid >> 5;
    int nb = ng * 4;

    float ar[4][4], az[4][4], ain[4][4], ahn[4][4];
#pragma unroll
    for (int i = 0; i < 4; ++i) {
        int gn = min(n0 + nb + i, NN - 1);
        const float4* g4 = (const float4*)(g_gi + gn * 192);
        float4 r4 = g4[hg];        // j offset hg*4       (r chunk)
        float4 z4 = g4[16 + hg];   // 64 + hg*4           (z chunk)
        float4 i4 = g4[32 + hg];   // 128 + hg*4          (i_n chunk)
        ar[i][0] = r4.x; ar[i][1] = r4.y; ar[i][2] = r4.z; ar[i][3] = r4.w;
        az[i][0] = z4.x; az[i][1] = z4.y; az[i][2] = z4.z; az[i][3] = z4.w;
        ain[i][0] = i4.x; ain[i][1] = i4.y; ain[i][2] = i4.z; ain[i][3] = i4.w;
#pragma unroll
        for (int j = 0; j < 4; ++j) ahn[i][j] = s_bhn[hg * 4 + j];
    }

    // ---- K = 64 over h_prev: r, z, h_n ----
#pragma unroll 4
    for (int k = 0; k < 64; ++k) {
        float4 xv = *(const float4*)(s_zt + k * 128 + nb);
        const float* wp = s_whh + k * 192 + (hg << 2);
        float4 wr = *(const float4*)(wp);
        float4 wz = *(const float4*)(wp + 64);
        float4 wn = *(const float4*)(wp + 128);
        float xa[4]  = {xv.x, xv.y, xv.z, xv.w};
        float wra[4] = {wr.x, wr.y, wr.z, wr.w};
        float wza[4] = {wz.x, wz.y, wz.z, wz.w};
        float wna[4] = {wn.x, wn.y, wn.z, wn.w};
#pragma unroll
        for (int i = 0; i < 4; ++i)
#pragma unroll
            for (int j = 0; j < 4; ++j) {
                ar[i][j]  = fmaf(xa[i], wra[j], ar[i][j]);
                az[i][j]  = fmaf(xa[i], wza[j], az[i][j]);
                ahn[i][j] = fmaf(xa[i], wna[j], ahn[i][j]);
            }
    }
    // ---- K = 8 over x_dyn: r, z, i_n ----
#pragma unroll
    for (int k = 0; k < 8; ++k) {
        float4 xv = *(const float4*)(s_zt + (64 + k) * 128 + nb);
        const float* wp = s_wih8 + k * 192 + (hg << 2);
        float4 wr = *(const float4*)(wp);
        float4 wz = *(const float4*)(wp + 64);
        float4 wi = *(const float4*)(wp + 128);
        float xa[4]  = {xv.x, xv.y, xv.z, xv.w};
        float wra[4] = {wr.x, wr.y, wr.z, wr.w};
        float wza[4] = {wz.x, wz.y, wz.z, wz.w};
        float wia[4] = {wi.x, wi.y, wi.z, wi.w};
#pragma unroll
        for (int i = 0; i < 4; ++i)
#pragma unroll
            for (int j = 0; j < 4; ++j) {
                ar[i][j]  = fmaf(xa[i], wra[j], ar[i][j]);
                az[i][j]  = fmaf(xa[i], wza[j], az[i][j]);
                ain[i][j] = fmaf(xa[i], wia[j], ain[i][j]);
            }
    }

    __syncthreads();   // all s_zt reads done; safe to overlay hnew
    float* s_hnew = s_zt;   // [64][128]

    // ---- gates + state update ----
#pragma unroll
    for (int i = 0; i < 4; ++i) {
        int nl = nb + i;
        int gn = n0 + nl;
        bool valid = gn < NN;
        int gcl = valid ? gn : (NN - 1);
        float4 hp = *(const float4*)(hprev + gcl * 64 + (hg << 2));
        float hpa[4] = {hp.x, hp.y, hp.z, hp.w};
        float hv[4];
#pragma unroll
        for (int j = 0; j < 4; ++j) {
            float r  = sigf(ar[i][j]);
            float zz = sigf(az[i][j]);
            float nn = tanhx(ain[i][j] + r * ahn[i][j]);
            float h  = nn + zz * (hpa[j] - nn);
            hv[j] = h;
            s_hnew[(hg * 4 + j) * 128 + nl] = h;
        }
        if (valid)
            *(float4*)(hnext + gn * 64 + (hg << 2)) = make_float4(hv[0], hv[1], hv[2], hv[3]);
    }
    __syncthreads();

    // ---- fused MLP head: 4 threads per node ----
    {
        int nl = tid >> 2, p = tid & 3;
        float acc[16];
#pragma unroll
        for (int jj = 0; jj < 16; ++jj) acc[jj] = s_h1b[p * 16 + jj];
#pragma unroll 2
        for (int k = 0; k < 64; ++k) {
            float hvv = s_hnew[k * 128 + nl];
            const float4* w4 = (const float4*)(s_h1w + k * 64 + (p << 4));
            float4 w0 = w4[0], w1 = w4[1], w2 = w4[2], w3 = w4[3];
            acc[0]  = fmaf(hvv, w0.x, acc[0]);  acc[1]  = fmaf(hvv, w0.y, acc[1]);
            acc[2]  = fmaf(hvv, w0.z, acc[2]);  acc[3]  = fmaf(hvv, w0.w, acc[3]);
            acc[4]  = fmaf(hvv, w1.x, acc[4]);  acc[5]  = fmaf(hvv, w1.y, acc[5]);
            acc[6]  = fmaf(hvv, w1.z, acc[6]);  acc[7]  = fmaf(hvv, w1.w, acc[7]);
            acc[8]  = fmaf(hvv, w2.x, acc[8]);  acc[9]  = fmaf(hvv, w2.y, acc[9]);
            acc[10] = fmaf(hvv, w2.z, acc[10]); acc[11] = fmaf(hvv, w2.w, acc[11]);
            acc[12] = fmaf(hvv, w3.x, acc[12]); acc[13] = fmaf(hvv, w3.y, acc[13]);
            acc[14] = fmaf(hvv, w3.z, acc[14]); acc[15] = fmaf(hvv, w3.w, acc[15]);
        }
        float part = 0.0f;
#pragma unroll
        for (int jj = 0; jj < 16; ++jj)
            part = fmaf(s_h2w[p * 16 + jj], fmaxf(acc[jj], 0.0f), part);
        part += __shfl_xor_sync(0xffffffffu, part, 1);
        part += __shfl_xor_sync(0xffffffffu, part, 2);
        int gn = n0 + nl;
        if (p == 0 && gn < NN)
            yout[gn] = sigf(part + s_h2b[0]);
    }
}

// ----------------------------------------------------------------------------
// Launch
// ----------------------------------------------------------------------------
extern "C" void kernel_launch(void* const* d_in, const int* in_sizes, int n_in,
                              void* d_out, int out_size) {
    const float* X_static = (const float*)d_in[0];
    const float* X_dyn    = (const float*)d_in[1];
    const int*   er       = (const int*)d_in[2];
    const int*   ec       = (const int*)d_in[3];
    const float* ev       = (const float*)d_in[4];
    const float* g1W      = (const float*)d_in[5];
    const float* g1b      = (const float*)d_in[6];
    const float* g2W      = (const float*)d_in[7];
    const float* g2b      = (const float*)d_in[8];
    const float* Wih      = (const float*)d_in[9];
    const float* Whh      = (const float*)d_in[10];
    const float* bih      = (const float*)d_in[11];
    const float* bhh      = (const float*)d_in[12];
    const float* h1W      = (const float*)d_in[13];
    const float* h1b      = (const float*)d_in[14];
    const float* h2W      = (const float*)d_in[15];
    const float* h2b      = (const float*)d_in[16];
    float* out = (float*)d_out;

    cudaFuncSetAttribute(gru_step_kernel,
                         cudaFuncAttributeMaxDynamicSharedMemorySize, SMEM_BYTES);

    // GraphConv layer 1
    zero_acc_kernel<<<12500, 256>>>();
    lin32_kernel<<<12500, 256>>>(X_static, g1W, g1b, 0);
    spmm_kernel<<<400000, 256>>>(er, ec, ev);

    // GraphConv layer 2 (relu on read of g_acc)
    lin32_kernel<<<12500, 256>>>(X_static /*unused*/, g2W, g2b, 1);
    zero_acc_kernel<<<12500, 256>>>();
    spmm_kernel<<<400000, 256>>>(er, ec, ev);

    // Time-invariant gate projections (+combined biases), weight transposes, h0=0
    gi_static_kernel<<<3125, 256>>>(Wih, bih, bhh);
    prep_weights_kernel<<<36, 512>>>(Whh, Wih, h1W, bhh);
    zero_h0_kernel<<<25000, 256>>>();

    // GRU recurrence with fused MLP head
    for (int t = 0; t < TT; ++t) {
        gru_step_kernel<<<782, 512, SMEM_BYTES>>>(
            X_dyn + (size_t)t * NN * 8, h1b, h2W, h2b,
            out + (size_t)t * NN, t & 1);
    }
}

// round 2
// speedup vs baseline: 1.0809x; 1.0809x over previous
#include <cuda_runtime.h>
#include <math.h>

#define DINLINE __device__ __forceinline__
typedef unsigned long long u64;

constexpr int NN = 100000;   // nodes
constexpr int TT = 24;       // time steps
constexpr int EE = 3200000;  // edges

// ----------------------------------------------------------------------------
// Scratch (static device globals; no allocations allowed)
// ----------------------------------------------------------------------------
__device__ __align__(16) float g_xw[NN * 32];      // linear output / spmm input
__device__ __align__(16) float g_acc[NN * 32];     // spmm accumulator
__device__ __align__(16) float g_gi[NN * 192];     // time-invariant input-gate projections (+bias)
__device__ __align__(16) float g_h[2][NN * 64];    // double-buffered GRU state
__device__ __align__(16) float g_WhhT[64 * 192];   // W_hh transposed: [k][j]  (j order: r|z|n)
__device__ __align__(16) float g_Wih8T[8 * 192];   // W_ih[:,32:40] transposed: [k8][j]
__device__ __align__(16) float g_h1wT[64 * 64];    // h1_W transposed: [k][j]
__device__ __align__(16) float g_bhn[64];          // b_hh[128:192]

DINLINE float sigf(float x)  { return __fdividef(1.0f, 1.0f + __expf(-x)); }
DINLINE float tanhx(float x) { return __fdividef(2.0f, 1.0f + __expf(-2.0f * x)) - 1.0f; }

// f32x2 packed math (sm_103a FFMA2 — only reachable via PTX)
DINLINE u64 pack2(float lo, float hi) {
    u64 r; asm("mov.b64 %0, {%1, %2};" : "=l"(r) : "f"(lo), "f"(hi)); return r;
}
DINLINE void unpack2(u64 v, float& lo, float& hi) {
    asm("mov.b64 {%0, %1}, %2;" : "=f"(lo), "=f"(hi) : "l"(v));
}
DINLINE u64 fma2(u64 a, u64 b, u64 c) {
    u64 d; asm("fma.rn.f32x2 %0, %1, %2, %3;" : "=l"(d) : "l"(a), "l"(b), "l"(c)); return d;
}

// ----------------------------------------------------------------------------
// Zeroing kernels (grid sizes are exact multiples; no bounds checks needed)
// ----------------------------------------------------------------------------
__global__ void zero_acc_kernel() {
    int i = blockIdx.x * 256 + threadIdx.x;   // grid = 12500*256 = N*32 exactly
    g_acc[i] = 0.0f;
}
__global__ void zero_h0_kernel() {
    int i = blockIdx.x * 256 + threadIdx.x;   // grid = 25000*256 = N*64 exactly
    g_h[0][i] = 0.0f;
}

// ----------------------------------------------------------------------------
// Dense 32->32 linear: g_xw[n][j] = src[n][:] @ W[j][:]^T + b[j]
// 32 nodes / 256-thread block (4 nodes per thread); grid = 3125 exactly.
// ----------------------------------------------------------------------------
__global__ void lin32_kernel(const float* __restrict__ Xext,
                             const float* __restrict__ W,
                             const float* __restrict__ bias,
                             int relu_acc_src) {
    __shared__ float Wt[1024];      // Wt[k*32+j] = W[j][k]
    __shared__ float Xs[32 * 33];   // 32 nodes, padded rows
    int tid = threadIdx.x;
    int n0  = blockIdx.x * 32;

    for (int e = tid; e < 1024; e += 256) {
        int j = e >> 5, k = e & 31;
        Wt[k * 32 + j] = W[j * 32 + k];
    }
    for (int e = tid; e < 1024; e += 256) {
        int n = e >> 5, k = e & 31;
        float v;
        if (relu_acc_src) v = fmaxf(g_acc[(n0 + n) * 32 + k], 0.0f);
        else              v = Xext[(n0 + n) * 32 + k];
        Xs[n * 33 + k] = v;
    }
    __syncthreads();

    int j = tid & 31;
    float b = bias[j];
#pragma unroll
    for (int g = 0; g < 4; ++g) {
        int n = (tid >> 5) + g * 8;
        float acc = b;
#pragma unroll
        for (int k = 0; k < 32; ++k)
            acc = fmaf(Xs[n * 33 + k], Wt[k * 32 + j], acc);
        g_xw[(n0 + n) * 32 + j] = acc;
    }
}

// ----------------------------------------------------------------------------
// SpMM scatter with vector REDs: 8 threads / edge, one v4 red each.
// grid = E*8/256 = 100000 blocks exactly.
// ----------------------------------------------------------------------------
__global__ void spmm_kernel(const int*  __restrict__ er,
                            const int*  __restrict__ ec,
                            const float* __restrict__ ev) {
    int idx = blockIdx.x * 256 + threadIdx.x;
    int e = idx >> 3, q = idx & 7;
    int r = __ldg(er + e);
    int c = __ldg(ec + e);
    float v = __ldg(ev + e);
    float4 x = *(const float4*)(g_xw + c * 32 + q * 4);
    float* dst = g_acc + r * 32 + q * 4;
    asm volatile("red.global.add.v4.f32 [%0], {%1, %2, %3, %4};"
                 :: "l"(dst), "f"(v * x.x), "f"(v * x.y), "f"(v * x.z), "f"(v * x.w)
                 : "memory");
}

// ----------------------------------------------------------------------------
// gi_static[n][j] = relu(g_acc[n]) @ W_ih[j,0:32]^T + b_ih[j] + (j<128 ? b_hh[j] : 0)
// 32 nodes / 256-thread block; grid = 3125 exactly.
// ----------------------------------------------------------------------------
__global__ void gi_static_kernel(const float* __restrict__ Wih,
                                 const float* __restrict__ bih,
                                 const float* __restrict__ bhh) {
    __shared__ float Ws[32 * 192];   // Ws[k*192+j] = W_ih[j][k]
    __shared__ float Hs[32 * 33];    // relu'd h tile, padded rows
    int tid = threadIdx.x;
    int n0  = blockIdx.x * 32;

    for (int e = tid; e < 6144; e += 256) {
        int k = e / 192, j = e - k * 192;
        Ws[e] = Wih[j * 40 + k];
    }
    for (int e = tid; e < 1024; e += 256) {
        int n = e >> 5, k = e & 31;
        Hs[n * 33 + k] = fmaxf(g_acc[(n0 + n) * 32 + k], 0.0f);
    }
    __syncthreads();

#pragma unroll 1
    for (int it = 0; it < 24; ++it) {
        int p = it * 256 + tid;        // 32*192 = 6144 = 24*256
        int n = p / 192, j = p - n * 192;
        float acc = bih[j] + (j < 128 ? bhh[j] : 0.0f);
#pragma unroll
        for (int k = 0; k < 32; ++k)
            acc = fmaf(Hs[n * 33 + k], Ws[k * 192 + j], acc);
        g_gi[(n0 + n) * 192 + j] = acc;
    }
}

// ----------------------------------------------------------------------------
// Transpose weights once per launch into fast-load layouts.
// ----------------------------------------------------------------------------
__global__ void prep_weights_kernel(const float* __restrict__ Whh,
                                    const float* __restrict__ Wih,
                                    const float* __restrict__ h1W,
                                    const float* __restrict__ bhh) {
    int id = blockIdx.x * 512 + threadIdx.x;
    if (id < 12288) {                       // W_hh: [192][64] -> [64][192]
        int k = id / 192, j = id - k * 192;
        g_WhhT[id] = Whh[j * 64 + k];
    } else if (id < 13824) {                // W_ih cols 32..39: [192][8] -> [8][192]
        int q = id - 12288;
        int k = q / 192, j = q - k * 192;
        g_Wih8T[q] = Wih[j * 40 + 32 + k];
    } else if (id < 17920) {                // h1_W: [64][64] -> [64][64] transposed
        int q = id - 13824;
        int k = q >> 6, j = q & 63;
        g_h1wT[q] = h1W[j * 64 + k];
    } else if (id < 17984) {
        g_bhn[id - 17920] = bhh[128 + id - 17920];
    }
}

// ----------------------------------------------------------------------------
// Fused GRU step + MLP head. 128 nodes / 512-thread block.
// Thread (ng = tid&31, hg = tid>>5) owns 4 nodes x 4 hidden units (as 2 f32x2
// j-pairs) x {r,z,in,hn} — packed FFMA2 math throughout.
// ----------------------------------------------------------------------------
constexpr int SMEM_FLOATS = 9216 + 12288 + 1536 + 4096 + 64 + 64 + 64 + 4;
constexpr int SMEM_BYTES  = SMEM_FLOATS * 4;   // 109,332 B

__global__ void __launch_bounds__(512, 1)
gru_step_kernel(const float* __restrict__ xdyn_t,   // X_dyn_mean + t*N*8
                const float* __restrict__ h1b,
                const float* __restrict__ h2w,
                const float* __restrict__ h2b,
                float* __restrict__ yout,           // d_out + t*N
                int parity) {
    extern __shared__ float sm[];
    float* s_zt   = sm;                 // [72][128]  (reused as hnew [64][128] later)
    float* s_whh  = sm + 9216;          // [64][192]
    float* s_wih8 = s_whh + 12288;      // [8][192]
    float* s_h1w  = s_wih8 + 1536;      // [64][64]
    float* s_bhn  = s_h1w + 4096;       // 64
    float* s_h1b  = s_bhn + 64;         // 64
    float* s_h2w  = s_h1b + 64;         // 64
    float* s_h2b  = s_h2w + 64;         // 1

    const float* hprev = g_h[parity];
    float*       hnext = g_h[parity ^ 1];
    int tid = threadIdx.x;
    int n0  = blockIdx.x * 128;

    // ---- prologue: weights ----
    {
        float4* d4; const float4* s4;
        d4 = (float4*)s_whh;  s4 = (const float4*)g_WhhT;
        for (int i = tid; i < 3072; i += 512) d4[i] = s4[i];
        d4 = (float4*)s_wih8; s4 = (const float4*)g_Wih8T;
        if (tid < 384) d4[tid] = s4[tid];
        d4 = (float4*)s_h1w;  s4 = (const float4*)g_h1wT;
        for (int i = tid; i < 1024; i += 512) d4[i] = s4[i];
        if (tid < 64) { s_bhn[tid] = g_bhn[tid]; s_h1b[tid] = h1b[tid]; s_h2w[tid] = h2w[tid]; }
        if (tid == 0) s_h2b[0] = h2b[0];
    }
    // ---- prologue: input tile, transposed [k][node] ----
    {
        int nl = tid >> 2, qp = tid & 3;
        int gn = min(n0 + nl, NN - 1);
        const float4* hp4 = (const float4*)hprev;
#pragma unroll
        for (int q = 0; q < 4; ++q) {
            int k0 = qp * 16 + q * 4;
            float4 v = hp4[gn * 16 + (k0 >> 2)];
            s_zt[(k0 + 0) * 128 + nl] = v.x;
            s_zt[(k0 + 1) * 128 + nl] = v.y;
            s_zt[(k0 + 2) * 128 + nl] = v.z;
            s_zt[(k0 + 3) * 128 + nl] = v.w;
        }
        if (tid < 128) {
            int gn2 = min(n0 + tid, NN - 1);
            const float4* x4 = (const float4*)(xdyn_t + gn2 * 8);
            float4 a = x4[0], b = x4[1];
            float* dst = s_zt + 64 * 128 + tid;
            dst[0] = a.x; dst[128] = a.y; dst[256] = a.z; dst[384] = a.w;
            dst[512] = b.x; dst[640] = b.y; dst[768] = b.z; dst[896] = b.w;
        }
    }
    __syncthreads();

    int ng = tid & 31, hg = tid >> 5;
    int nb = ng * 4;

    // Packed accumulators: [node i][j-pair]
    u64 ar2[4][2], az2[4][2], ain2[4][2], ahn2[4][2];
    {
        u64 bn0 = *(const u64*)(s_bhn + (hg << 2));
        u64 bn1 = *(const u64*)(s_bhn + (hg << 2) + 2);
#pragma unroll
        for (int i = 0; i < 4; ++i) {
            int gn = min(n0 + nb + i, NN - 1);
            const ulonglong2* g2 = (const ulonglong2*)(g_gi + gn * 192);
            ulonglong2 rv = g2[hg];         // j offset hg*4       (r chunk)
            ulonglong2 zv = g2[16 + hg];    // 64 + hg*4           (z chunk)
            ulonglong2 iv = g2[32 + hg];    // 128 + hg*4          (i_n chunk)
            ar2[i][0]  = rv.x; ar2[i][1]  = rv.y;
            az2[i][0]  = zv.x; az2[i][1]  = zv.y;
            ain2[i][0] = iv.x; ain2[i][1] = iv.y;
            ahn2[i][0] = bn0;  ahn2[i][1] = bn1;
        }
    }

    // ---- K = 64 over h_prev: r, z, h_n ----
#pragma unroll 4
    for (int k = 0; k < 64; ++k) {
        float4 xv = *(const float4*)(s_zt + k * 128 + nb);
        const float* wp = s_whh + k * 192 + (hg << 2);
        ulonglong2 wr = *(const ulonglong2*)(wp);
        ulonglong2 wz = *(const ulonglong2*)(wp + 64);
        ulonglong2 wn = *(const ulonglong2*)(wp + 128);
        u64 xd[4] = {pack2(xv.x, xv.x), pack2(xv.y, xv.y),
                     pack2(xv.z, xv.z), pack2(xv.w, xv.w)};
#pragma unroll
        for (int i = 0; i < 4; ++i) {
            ar2[i][0]  = fma2(xd[i], wr.x, ar2[i][0]);
            ar2[i][1]  = fma2(xd[i], wr.y, ar2[i][1]);
            az2[i][0]  = fma2(xd[i], wz.x, az2[i][0]);
            az2[i][1]  = fma2(xd[i], wz.y, az2[i][1]);
            ahn2[i][0] = fma2(xd[i], wn.x, ahn2[i][0]);
            ahn2[i][1] = fma2(xd[i], wn.y, ahn2[i][1]);
        }
    }
    // ---- K = 8 over x_dyn: r, z, i_n ----
#pragma unroll
    for (int k = 0; k < 8; ++k) {
        float4 xv = *(const float4*)(s_zt + (64 + k) * 128 + nb);
        const float* wp = s_wih8 + k * 192 + (hg << 2);
        ulonglong2 wr = *(const ulonglong2*)(wp);
        ulonglong2 wz = *(const ulonglong2*)(wp + 64);
        ulonglong2 wi = *(const ulonglong2*)(wp + 128);
        u64 xd[4] = {pack2(xv.x, xv.x), pack2(xv.y, xv.y),
                     pack2(xv.z, xv.z), pack2(xv.w, xv.w)};
#pragma unroll
        for (int i = 0; i < 4; ++i) {
            ar2[i][0]  = fma2(xd[i], wr.x, ar2[i][0]);
            ar2[i][1]  = fma2(xd[i], wr.y, ar2[i][1]);
            az2[i][0]  = fma2(xd[i], wz.x, az2[i][0]);
            az2[i][1]  = fma2(xd[i], wz.y, az2[i][1]);
            ain2[i][0] = fma2(xd[i], wi.x, ain2[i][0]);
            ain2[i][1] = fma2(xd[i], wi.y, ain2[i][1]);
        }
    }

    __syncthreads();   // all s_zt reads done; safe to overlay hnew
    float* s_hnew = s_zt;   // [64][128]

    // ---- gates + state update ----
#pragma unroll
    for (int i = 0; i < 4; ++i) {
        int nl = nb + i;
        int gn = n0 + nl;
        bool valid = gn < NN;
        int gcl = valid ? gn : (NN - 1);
        float4 hp = *(const float4*)(hprev + gcl * 64 + (hg << 2));
        float hpa[4] = {hp.x, hp.y, hp.z, hp.w};
        float hv[4];
#pragma unroll
        for (int jp = 0; jp < 2; ++jp) {
            float r0, r1, z0, z1, in0, in1, hn0, hn1;
            unpack2(ar2[i][jp],  r0,  r1);
            unpack2(az2[i][jp],  z0,  z1);
            unpack2(ain2[i][jp], in0, in1);
            unpack2(ahn2[i][jp], hn0, hn1);
            float ra = sigf(r0), rb = sigf(r1);
            float za = sigf(z0), zb = sigf(z1);
            float na = tanhx(in0 + ra * hn0);
            float nbv = tanhx(in1 + rb * hn1);
            float ha = na + za * (hpa[jp * 2 + 0] - na);
            float hb = nbv + zb * (hpa[jp * 2 + 1] - nbv);
            hv[jp * 2 + 0] = ha;
            hv[jp * 2 + 1] = hb;
            s_hnew[(hg * 4 + jp * 2 + 0) * 128 + nl] = ha;
            s_hnew[(hg * 4 + jp * 2 + 1) * 128 + nl] = hb;
        }
        if (valid)
            *(float4*)(hnext + gn * 64 + (hg << 2)) = make_float4(hv[0], hv[1], hv[2], hv[3]);
    }
    __syncthreads();

    // ---- fused MLP head: 4 threads per node, packed f32x2 ----
    {
        int nl = tid >> 2, p = tid & 3;
        u64 acc2[8];
        const u64* b2 = (const u64*)(s_h1b + (p << 4));
#pragma unroll
        for (int jj = 0; jj < 8; ++jj) acc2[jj] = b2[jj];
#pragma unroll 2
        for (int k = 0; k < 64; ++k) {
            float hvv = s_hnew[k * 128 + nl];
            u64 hd = pack2(hvv, hvv);
            const ulonglong2* w2 = (const ulonglong2*)(s_h1w + k * 64 + (p << 4));
            ulonglong2 wa = w2[0], wb = w2[1], wc = w2[2], wd = w2[3];
            acc2[0] = fma2(hd, wa.x, acc2[0]); acc2[1] = fma2(hd, wa.y, acc2[1]);
            acc2[2] = fma2(hd, wb.x, acc2[2]); acc2[3] = fma2(hd, wb.y, acc2[3]);
            acc2[4] = fma2(hd, wc.x, acc2[4]); acc2[5] = fma2(hd, wc.y, acc2[5]);
            acc2[6] = fma2(hd, wd.x, acc2[6]); acc2[7] = fma2(hd, wd.y, acc2[7]);
        }
        float part = 0.0f;
#pragma unroll
        for (int jj = 0; jj < 8; ++jj) {
            float u, v;
            unpack2(acc2[jj], u, v);
            part = fmaf(s_h2w[(p << 4) + jj * 2 + 0], fmaxf(u, 0.0f), part);
            part = fmaf(s_h2w[(p << 4) + jj * 2 + 1], fmaxf(v, 0.0f), part);
        }
        part += __shfl_xor_sync(0xffffffffu, part, 1);
        part += __shfl_xor_sync(0xffffffffu, part, 2);
        int gn = n0 + nl;
        if (p == 0 && gn < NN)
            yout[gn] = sigf(part + s_h2b[0]);
    }
}

// ----------------------------------------------------------------------------
// Launch
// ----------------------------------------------------------------------------
extern "C" void kernel_launch(void* const* d_in, const int* in_sizes, int n_in,
                              void* d_out, int out_size) {
    const float* X_static = (const float*)d_in[0];
    const float* X_dyn    = (const float*)d_in[1];
    const int*   er       = (const int*)d_in[2];
    const int*   ec       = (const int*)d_in[3];
    const float* ev       = (const float*)d_in[4];
    const float* g1W      = (const float*)d_in[5];
    const float* g1b      = (const float*)d_in[6];
    const float* g2W      = (const float*)d_in[7];
    const float* g2b      = (const float*)d_in[8];
    const float* Wih      = (const float*)d_in[9];
    const float* Whh      = (const float*)d_in[10];
    const float* bih      = (const float*)d_in[11];
    const float* bhh      = (const float*)d_in[12];
    const float* h1W      = (const float*)d_in[13];
    const float* h1b      = (const float*)d_in[14];
    const float* h2W      = (const float*)d_in[15];
    const float* h2b      = (const float*)d_in[16];
    float* out = (float*)d_out;

    cudaFuncSetAttribute(gru_step_kernel,
                         cudaFuncAttributeMaxDynamicSharedMemorySize, SMEM_BYTES);

    // GraphConv layer 1
    zero_acc_kernel<<<12500, 256>>>();
    lin32_kernel<<<3125, 256>>>(X_static, g1W, g1b, 0);
    spmm_kernel<<<100000, 256>>>(er, ec, ev);

    // GraphConv layer 2 (relu on read of g_acc)
    lin32_kernel<<<3125, 256>>>(X_static /*unused*/, g2W, g2b, 1);
    zero_acc_kernel<<<12500, 256>>>();
    spmm_kernel<<<100000, 256>>>(er, ec, ev);

    // Time-invariant gate projections (+combined biases), weight transposes, h0=0
    gi_static_kernel<<<3125, 256>>>(Wih, bih, bhh);
    prep_weights_kernel<<<36, 512>>>(Whh, Wih, h1W, bhh);
    zero_h0_kernel<<<25000, 256>>>();

    // GRU recurrence with fused MLP head
    for (int t = 0; t < TT; ++t) {
        gru_step_kernel<<<782, 512, SMEM_BYTES>>>(
            X_dyn + (size_t)t * NN * 8, h1b, h2W, h2b,
            out + (size_t)t * NN, t & 1);
    }
}

// round 3
// speedup vs baseline: 2.3339x; 2.1592x over previous
#include <cuda_runtime.h>
#include <math.h>

#define DINLINE __device__ __forceinline__
typedef unsigned long long u64;

constexpr int NN = 100000;   // nodes
constexpr int TT = 24;       // time steps
constexpr int EE = 3200000;  // edges

// ----------------------------------------------------------------------------
// Scratch (static device globals; no allocations allowed)
// ----------------------------------------------------------------------------
__device__ __align__(16) float g_xw[NN * 32];      // linear output / spmm input
__device__ __align__(16) float g_acc[NN * 32];     // spmm accumulator
__device__ __align__(16) float g_gi[NN * 192];     // time-invariant input-gate projections (+bias)
__device__ __align__(16) float g_WhhT[64 * 192];   // W_hh transposed: [k][j]  (j order: r|z|n)
__device__ __align__(16) float g_Wih8T[8 * 192];   // W_ih[:,32:40] transposed: [k8][j]
__device__ __align__(16) float g_h1wT[64 * 64];    // h1_W transposed: [k][j]
__device__ __align__(16) float g_bhn[64];          // b_hh[128:192]

DINLINE float sigf(float x)  { return __fdividef(1.0f, 1.0f + __expf(-x)); }
DINLINE float tanhx(float x) { return __fdividef(2.0f, 1.0f + __expf(-2.0f * x)) - 1.0f; }

// f32x2 packed math (sm_103a FFMA2 — only reachable via PTX)
DINLINE u64 pack2(float lo, float hi) {
    u64 r; asm("mov.b64 %0, {%1, %2};" : "=l"(r) : "f"(lo), "f"(hi)); return r;
}
DINLINE void unpack2(u64 v, float& lo, float& hi) {
    asm("mov.b64 {%0, %1}, %2;" : "=f"(lo), "=f"(hi) : "l"(v));
}
DINLINE u64 fma2(u64 a, u64 b, u64 c) {
    u64 d; asm("fma.rn.f32x2 %0, %1, %2, %3;" : "=l"(d) : "l"(a), "l"(b), "l"(c)); return d;
}

// ----------------------------------------------------------------------------
// Dense 32->32 linear + g_acc zeroing. 32 nodes / 256-thread block; grid 3125.
// ----------------------------------------------------------------------------
__global__ void lin32_kernel(const float* __restrict__ Xext,
                             const float* __restrict__ W,
                             const float* __restrict__ bias,
                             int relu_acc_src) {
    __shared__ float Wt[1024];      // Wt[k*32+j] = W[j][k]
    __shared__ float Xs[32 * 33];   // 32 nodes, padded rows
    int tid = threadIdx.x;
    int n0  = blockIdx.x * 32;

    for (int e = tid; e < 1024; e += 256) {
        int j = e >> 5, k = e & 31;
        Wt[k * 32 + j] = W[j * 32 + k];
    }
    for (int e = tid; e < 1024; e += 256) {
        int n = e >> 5, k = e & 31;
        float v;
        if (relu_acc_src) v = fmaxf(g_acc[(n0 + n) * 32 + k], 0.0f);
        else              v = Xext[(n0 + n) * 32 + k];
        Xs[n * 33 + k] = v;
    }
    __syncthreads();

    // zero this block's g_acc slice for the following spmm
    for (int e = tid; e < 1024; e += 256)
        g_acc[n0 * 32 + e] = 0.0f;

    int j = tid & 31;
    float b = bias[j];
#pragma unroll
    for (int g = 0; g < 4; ++g) {
        int n = (tid >> 5) + g * 8;
        float acc = b;
#pragma unroll
        for (int k = 0; k < 32; ++k)
            acc = fmaf(Xs[n * 33 + k], Wt[k * 32 + j], acc);
        g_xw[(n0 + n) * 32 + j] = acc;
    }
}

// ----------------------------------------------------------------------------
// SpMM scatter with vector REDs: 8 threads / edge, one v4 red each.
// grid = E*8/256 = 100000 blocks exactly.
// ----------------------------------------------------------------------------
__global__ void spmm_kernel(const int*  __restrict__ er,
                            const int*  __restrict__ ec,
                            const float* __restrict__ ev) {
    int idx = blockIdx.x * 256 + threadIdx.x;
    int e = idx >> 3, q = idx & 7;
    int r = __ldg(er + e);
    int c = __ldg(ec + e);
    float v = __ldg(ev + e);
    float4 x = *(const float4*)(g_xw + c * 32 + q * 4);
    float* dst = g_acc + r * 32 + q * 4;
    asm volatile("red.global.add.v4.f32 [%0], {%1, %2, %3, %4};"
                 :: "l"(dst), "f"(v * x.x), "f"(v * x.y), "f"(v * x.z), "f"(v * x.w)
                 : "memory");
}

// ----------------------------------------------------------------------------
// gi_static + weight prep (fused). 32 nodes / 256-thread block; grid 3125.
// ----------------------------------------------------------------------------
__global__ void gi_prep_kernel(const float* __restrict__ Wih,
                               const float* __restrict__ bih,
                               const float* __restrict__ bhh,
                               const float* __restrict__ Whh,
                               const float* __restrict__ h1W) {
    __shared__ float Ws[32 * 192];   // Ws[k*192+j] = W_ih[j][k]
    __shared__ float Hs[32 * 33];    // relu'd h tile, padded rows
    int tid = threadIdx.x;
    int n0  = blockIdx.x * 32;

    // weight-prep side work on the first 36 blocks (2 ids each thread)
    if (blockIdx.x < 36) {
#pragma unroll
        for (int h = 0; h < 2; ++h) {
            int id = blockIdx.x * 512 + h * 256 + tid;
            if (id < 12288) {                       // W_hh: [192][64] -> [64][192]
                int k = id / 192, j = id - k * 192;
                g_WhhT[id] = Whh[j * 64 + k];
            } else if (id < 13824) {                // W_ih cols 32..39 -> [8][192]
                int q = id - 12288;
                int k = q / 192, j = q - k * 192;
                g_Wih8T[q] = Wih[j * 40 + 32 + k];
            } else if (id < 17920) {                // h1_W -> transposed [64][64]
                int q = id - 13824;
                int k = q >> 6, j = q & 63;
                g_h1wT[q] = h1W[j * 64 + k];
            } else if (id < 17984) {
                g_bhn[id - 17920] = bhh[128 + id - 17920];
            }
        }
    }

    for (int e = tid; e < 6144; e += 256) {
        int k = e / 192, j = e - k * 192;
        Ws[e] = Wih[j * 40 + k];
    }
    for (int e = tid; e < 1024; e += 256) {
        int n = e >> 5, k = e & 31;
        Hs[n * 33 + k] = fmaxf(g_acc[(n0 + n) * 32 + k], 0.0f);
    }
    __syncthreads();

#pragma unroll 1
    for (int it = 0; it < 24; ++it) {
        int p = it * 256 + tid;        // 32*192 = 6144 = 24*256
        int n = p / 192, j = p - n * 192;
        float acc = bih[j] + (j < 128 ? bhh[j] : 0.0f);
#pragma unroll
        for (int k = 0; k < 32; ++k)
            acc = fmaf(Hs[n * 33 + k], Ws[k * 192 + j], acc);
        g_gi[(n0 + n) * 192 + j] = acc;
    }
}

// ----------------------------------------------------------------------------
// Persistent GRU: one block = 128 nodes, all 24 time steps + fused MLP head.
// h state lives in smem the whole time; gi loaded once per tile.
// Thread (ng = tid&31, hg = tid>>5) owns 4 nodes x 4 hidden units.
// ----------------------------------------------------------------------------
// smem layout (floats):
//   s_zt   [72*128]  = 9216   @ 0
//   s_gi   [12288 u64]        @ 9216   (24576 floats)
//   s_whh  [64*192]  = 12288  @ 33792
//   s_wih8 [8*192]   = 1536   @ 46080
//   s_h1w  [64*64]   = 4096   @ 47616
//   s_red  [16*128]  = 2048   @ 51712
//   s_bhn  64                 @ 53760
//   s_h1b  64                 @ 53824
//   s_h2w  64                 @ 53888
//   s_h2b  4                  @ 53952
constexpr int GRU_SMEM_FLOATS = 53956;
constexpr int GRU_SMEM_BYTES  = GRU_SMEM_FLOATS * 4;   // 215,824 B

__global__ void __launch_bounds__(512, 1)
gru_persistent_kernel(const float* __restrict__ xdyn,   // X_dyn_mean base
                      const float* __restrict__ h1b,
                      const float* __restrict__ h2w,
                      const float* __restrict__ h2b,
                      float* __restrict__ yout) {        // d_out base
    extern __shared__ float sm[];
    float* s_zt   = sm;
    u64*   s_gi   = (u64*)(sm + 9216);
    float* s_whh  = sm + 33792;
    float* s_wih8 = sm + 46080;
    float* s_h1w  = sm + 47616;
    float* s_red  = sm + 51712;
    float* s_bhn  = sm + 53760;
    float* s_h1b  = sm + 53824;
    float* s_h2w  = sm + 53888;
    float* s_h2b  = sm + 53952;

    int tid = threadIdx.x;
    int n0  = blockIdx.x * 128;
    int ng = tid & 31, hg = tid >> 5;
    int nb = ng * 4;

    // ---- prologue: weights & biases ----
    {
        float4* d4; const float4* s4;
        d4 = (float4*)s_whh;  s4 = (const float4*)g_WhhT;
        for (int i = tid; i < 3072; i += 512) d4[i] = s4[i];
        d4 = (float4*)s_wih8; s4 = (const float4*)g_Wih8T;
        if (tid < 384) d4[tid] = s4[tid];
        d4 = (float4*)s_h1w;  s4 = (const float4*)g_h1wT;
        for (int i = tid; i < 1024; i += 512) d4[i] = s4[i];
        if (tid < 64) { s_bhn[tid] = g_bhn[tid]; s_h1b[tid] = h1b[tid]; s_h2w[tid] = h2w[tid]; }
        if (tid == 0) s_h2b[0] = h2b[0];
    }
    // ---- prologue: gi slice for this thread's 4 nodes (kept all 24 steps) ----
#pragma unroll
    for (int i = 0; i < 4; ++i) {
        int gn = min(n0 + nb + i, NN - 1);
        const ulonglong2* g2 = (const ulonglong2*)(g_gi + gn * 192);
        ulonglong2 rv = g2[hg];         // r chunk
        ulonglong2 zv = g2[16 + hg];    // z chunk
        ulonglong2 iv = g2[32 + hg];    // i_n chunk
        s_gi[(i * 6 + 0) * 512 + tid] = rv.x;
        s_gi[(i * 6 + 1) * 512 + tid] = rv.y;
        s_gi[(i * 6 + 2) * 512 + tid] = zv.x;
        s_gi[(i * 6 + 3) * 512 + tid] = zv.y;
        s_gi[(i * 6 + 4) * 512 + tid] = iv.x;
        s_gi[(i * 6 + 5) * 512 + tid] = iv.y;
    }
    // ---- prologue: h0 = 0 ----
    for (int i = tid; i < 8192; i += 512) s_zt[i] = 0.0f;
    __syncthreads();

    u64 bn0 = *(const u64*)(s_bhn + (hg << 2));
    u64 bn1 = *(const u64*)(s_bhn + (hg << 2) + 2);
    u64 hb0 = *(const u64*)(s_h1b + (hg << 2));
    u64 hb1 = *(const u64*)(s_h1b + (hg << 2) + 2);
    float w2a = s_h2w[(hg << 2) + 0], w2b = s_h2w[(hg << 2) + 1];
    float w2c = s_h2w[(hg << 2) + 2], w2d = s_h2w[(hg << 2) + 3];

#pragma unroll 1
    for (int t = 0; t < TT; ++t) {
        // ---- stage x_dyn(t) into rows 64..71 (disjoint from rows 0..63) ----
        if (tid < 128) {
            int gn2 = min(n0 + tid, NN - 1);
            const float4* x4 = (const float4*)(xdyn + ((size_t)t * NN + gn2) * 8);
            float4 a = x4[0], b = x4[1];
            float* dst = s_zt + 64 * 128 + tid;
            dst[0] = a.x; dst[128] = a.y; dst[256] = a.z; dst[384] = a.w;
            dst[512] = b.x; dst[640] = b.y; dst[768] = b.z; dst[896] = b.w;
        }
        __syncthreads();

        // ---- init accumulators from resident gi ----
        u64 ar2[4][2], az2[4][2], ain2[4][2], ahn2[4][2];
#pragma unroll
        for (int i = 0; i < 4; ++i) {
            ar2[i][0]  = s_gi[(i * 6 + 0) * 512 + tid];
            ar2[i][1]  = s_gi[(i * 6 + 1) * 512 + tid];
            az2[i][0]  = s_gi[(i * 6 + 2) * 512 + tid];
            az2[i][1]  = s_gi[(i * 6 + 3) * 512 + tid];
            ain2[i][0] = s_gi[(i * 6 + 4) * 512 + tid];
            ain2[i][1] = s_gi[(i * 6 + 5) * 512 + tid];
            ahn2[i][0] = bn0;  ahn2[i][1] = bn1;
        }

        // ---- K = 64 over h_prev: r, z, h_n ----
#pragma unroll 4
        for (int k = 0; k < 64; ++k) {
            float4 xv = *(const float4*)(s_zt + k * 128 + nb);
            const float* wp = s_whh + k * 192 + (hg << 2);
            ulonglong2 wr = *(const ulonglong2*)(wp);
            ulonglong2 wz = *(const ulonglong2*)(wp + 64);
            ulonglong2 wn = *(const ulonglong2*)(wp + 128);
            u64 xd[4] = {pack2(xv.x, xv.x), pack2(xv.y, xv.y),
                         pack2(xv.z, xv.z), pack2(xv.w, xv.w)};
#pragma unroll
            for (int i = 0; i < 4; ++i) {
                ar2[i][0]  = fma2(xd[i], wr.x, ar2[i][0]);
                ar2[i][1]  = fma2(xd[i], wr.y, ar2[i][1]);
                az2[i][0]  = fma2(xd[i], wz.x, az2[i][0]);
                az2[i][1]  = fma2(xd[i], wz.y, az2[i][1]);
                ahn2[i][0] = fma2(xd[i], wn.x, ahn2[i][0]);
                ahn2[i][1] = fma2(xd[i], wn.y, ahn2[i][1]);
            }
        }
        // ---- K = 8 over x_dyn: r, z, i_n ----
#pragma unroll
        for (int k = 0; k < 8; ++k) {
            float4 xv = *(const float4*)(s_zt + (64 + k) * 128 + nb);
            const float* wp = s_wih8 + k * 192 + (hg << 2);
            ulonglong2 wr = *(const ulonglong2*)(wp);
            ulonglong2 wz = *(const ulonglong2*)(wp + 64);
            ulonglong2 wi = *(const ulonglong2*)(wp + 128);
            u64 xd[4] = {pack2(xv.x, xv.x), pack2(xv.y, xv.y),
                         pack2(xv.z, xv.z), pack2(xv.w, xv.w)};
#pragma unroll
            for (int i = 0; i < 4; ++i) {
                ar2[i][0]  = fma2(xd[i], wr.x, ar2[i][0]);
                ar2[i][1]  = fma2(xd[i], wr.y, ar2[i][1]);
                az2[i][0]  = fma2(xd[i], wz.x, az2[i][0]);
                az2[i][1]  = fma2(xd[i], wz.y, az2[i][1]);
                ain2[i][0] = fma2(xd[i], wi.x, ain2[i][0]);
                ain2[i][1] = fma2(xd[i], wi.y, ain2[i][1]);
            }
        }
        __syncthreads();   // all s_zt reads done

        // ---- gates + in-place h update (own slots only) ----
#pragma unroll
        for (int i = 0; i < 4; ++i) {
            int nl = nb + i;
#pragma unroll
            for (int jp = 0; jp < 2; ++jp) {
                float r0, r1, z0, z1, in0, in1, hn0, hn1;
                unpack2(ar2[i][jp],  r0,  r1);
                unpack2(az2[i][jp],  z0,  z1);
                unpack2(ain2[i][jp], in0, in1);
                unpack2(ahn2[i][jp], hn0, hn1);
                float hpa = s_zt[(hg * 4 + jp * 2 + 0) * 128 + nl];
                float hpb = s_zt[(hg * 4 + jp * 2 + 1) * 128 + nl];
                float ra = sigf(r0), rb = sigf(r1);
                float za = sigf(z0), zb = sigf(z1);
                float na  = tanhx(in0 + ra * hn0);
                float nbv = tanhx(in1 + rb * hn1);
                float ha = na  + za * (hpa - na);
                float hb = nbv + zb * (hpb - nbv);
                s_zt[(hg * 4 + jp * 2 + 0) * 128 + nl] = ha;
                s_zt[(hg * 4 + jp * 2 + 1) * 128 + nl] = hb;
            }
        }
        __syncthreads();

        // ---- MLP head as broadcast-weight GEMM + smem reduction ----
        {
            u64 acc2[4][2];
#pragma unroll
            for (int i = 0; i < 4; ++i) { acc2[i][0] = hb0; acc2[i][1] = hb1; }
#pragma unroll 4
            for (int k = 0; k < 64; ++k) {
                float4 xv = *(const float4*)(s_zt + k * 128 + nb);
                ulonglong2 w = *(const ulonglong2*)(s_h1w + k * 64 + (hg << 2));
                u64 xd[4] = {pack2(xv.x, xv.x), pack2(xv.y, xv.y),
                             pack2(xv.z, xv.z), pack2(xv.w, xv.w)};
#pragma unroll
                for (int i = 0; i < 4; ++i) {
                    acc2[i][0] = fma2(xd[i], w.x, acc2[i][0]);
                    acc2[i][1] = fma2(xd[i], w.y, acc2[i][1]);
                }
            }
#pragma unroll
            for (int i = 0; i < 4; ++i) {
                float p0, p1, p2, p3;
                unpack2(acc2[i][0], p0, p1);
                unpack2(acc2[i][1], p2, p3);
                float part = w2a * fmaxf(p0, 0.0f) + w2b * fmaxf(p1, 0.0f)
                           + w2c * fmaxf(p2, 0.0f) + w2d * fmaxf(p3, 0.0f);
                s_red[hg * 128 + nb + i] = part;
            }
        }
        __syncthreads();

        if (tid < 128) {
            float s = 0.0f;
#pragma unroll
            for (int g = 0; g < 16; ++g) s += s_red[g * 128 + tid];
            int gn = n0 + tid;
            if (gn < NN)
                yout[(size_t)t * NN + gn] = sigf(s + s_h2b[0]);
        }
        // next iteration's xdyn store targets rows 64..71 (disjoint) — no sync needed
    }
}

// ----------------------------------------------------------------------------
// Launch (6 kernels total)
// ----------------------------------------------------------------------------
extern "C" void kernel_launch(void* const* d_in, const int* in_sizes, int n_in,
                              void* d_out, int out_size) {
    const float* X_static = (const float*)d_in[0];
    const float* X_dyn    = (const float*)d_in[1];
    const int*   er       = (const int*)d_in[2];
    const int*   ec       = (const int*)d_in[3];
    const float* ev       = (const float*)d_in[4];
    const float* g1W      = (const float*)d_in[5];
    const float* g1b      = (const float*)d_in[6];
    const float* g2W      = (const float*)d_in[7];
    const float* g2b      = (const float*)d_in[8];
    const float* Wih      = (const float*)d_in[9];
    const float* Whh      = (const float*)d_in[10];
    const float* bih      = (const float*)d_in[11];
    const float* bhh      = (const float*)d_in[12];
    const float* h1W      = (const float*)d_in[13];
    const float* h1b      = (const float*)d_in[14];
    const float* h2W      = (const float*)d_in[15];
    const float* h2b      = (const float*)d_in[16];
    float* out = (float*)d_out;

    cudaFuncSetAttribute(gru_persistent_kernel,
                         cudaFuncAttributeMaxDynamicSharedMemorySize, GRU_SMEM_BYTES);

    // GraphConv layer 1 (lin32 also zeroes g_acc)
    lin32_kernel<<<3125, 256>>>(X_static, g1W, g1b, 0);
    spmm_kernel<<<100000, 256>>>(er, ec, ev);

    // GraphConv layer 2 (relu on read of g_acc, then re-zero)
    lin32_kernel<<<3125, 256>>>(X_static /*unused*/, g2W, g2b, 1);
    spmm_kernel<<<100000, 256>>>(er, ec, ev);

    // Time-invariant gate projections + weight prep (fused)
    gi_prep_kernel<<<3125, 256>>>(Wih, bih, bhh, Whh, h1W);

    // Persistent GRU: all 24 steps + MLP head in one launch
    gru_persistent_kernel<<<782, 512, GRU_SMEM_BYTES>>>(X_dyn, h1b, h2W, h2b, out);
}